// round 8
// baseline (speedup 1.0000x reference)
#include <cuda_runtime.h>
#include <cstdint>

// Problem constants (fixed by the reference)
#define HH 1024
#define WW 1024
#define HWSZ (HH * WW)      // 1,048,576 cells
#define NF 64               // features
#define NP 100000           // pillars

// Per-cell winner, encoded as (pillar_index + 1); 0 == empty.
// BSS zero-init makes the very first call correct; clear_winner_kernel
// (launched after gather) restores the all-empty state for the next replay.
__device__ __align__(16) int g_winner[HWSZ];

// coords is int32 on device (JAX x64-off materializes int64 as int32).
// Layout [NP, 3]: x = col 2, y = col 1. Last-writer-wins == max pillar idx.
__global__ __launch_bounds__(256) void scatter_winner_kernel(
        const int* __restrict__ coords) {
    int p = blockIdx.x * blockDim.x + threadIdx.x;
    if (p >= NP) return;
    int x = coords[3 * p + 2];
    int y = coords[3 * p + 1];
    if (x >= 0 && x < WW && y >= 0 && y < HH) {
        atomicMax(&g_winner[y * WW + x], p + 1);
    }
}

// One thread per (4-cell group, 16-feature slice): winner int4 read ONCE,
// then 4 chunk iterations of (4 predicated feat loads -> transpose -> 4
// STG.128). blockIdx.y = 16-feature slice (0..3).
// Winner L2 re-read traffic: 16MB total (vs 64MB at 1 chunk/thread) — the
// LTS throughput cap counts L2 hits, so this is real time.
// Output stores evict-first (.cs) to keep feat + winner L2-resident.
__global__ __launch_bounds__(256) void gather_out_kernel(
        const float* __restrict__ feat,
        float* __restrict__ out) {
    int g = blockIdx.x * blockDim.x + threadIdx.x;   // cell-group id
    int f16 = blockIdx.y;                             // 16-feature slice
    int c0 = g * 4;

    int4 w4 = __ldg(reinterpret_cast<const int4*>(&g_winner[c0]));
    int w[4] = {w4.x, w4.y, w4.z, w4.w};

    #pragma unroll
    for (int cc = 0; cc < 4; cc++) {
        int f4 = f16 * 4 + cc;                        // 4-feature chunk
        float4 v[4];
        #pragma unroll
        for (int j = 0; j < 4; j++) {
            if (w[j] > 0) {
                v[j] = __ldg(reinterpret_cast<const float4*>(
                    feat + (size_t)(w[j] - 1) * NF + f4 * 4));
            } else {
                v[j] = make_float4(0.f, 0.f, 0.f, 0.f);
            }
        }
        #pragma unroll
        for (int k = 0; k < 4; k++) {
            float4 o;
            o.x = reinterpret_cast<const float*>(&v[0])[k];
            o.y = reinterpret_cast<const float*>(&v[1])[k];
            o.z = reinterpret_cast<const float*>(&v[2])[k];
            o.w = reinterpret_cast<const float*>(&v[3])[k];
            __stcs(reinterpret_cast<float4*>(
                out + (size_t)(f4 * 4 + k) * HWSZ + c0), o);
        }
    }
}

// Restore the all-empty winner state for the next graph replay.
__global__ __launch_bounds__(512) void clear_winner_kernel() {
    int i = blockIdx.x * blockDim.x + threadIdx.x;
    if (i < HWSZ / 4) {
        reinterpret_cast<int4*>(g_winner)[i] = make_int4(0, 0, 0, 0);
    }
}

extern "C" void kernel_launch(void* const* d_in, const int* in_sizes, int n_in,
                              void* d_out, int out_size) {
    const float* pillar_features = (const float*)d_in[0]; // [NP, 64] f32
    const int*   coords          = (const int*)d_in[1];   // [NP, 3] i32
    float*       out             = (float*)d_out;         // [1,64,1024,1024] f32

    {
        int threads = 256;
        int blocks = (NP + threads - 1) / threads;
        scatter_winner_kernel<<<blocks, threads>>>(coords);
    }
    {
        int threads = 256;
        dim3 grid((HWSZ / 4) / threads, 4);   // 1024 x 4 blocks
        gather_out_kernel<<<grid, threads>>>(pillar_features, out);
    }
    {
        int threads = 512;
        int blocks = (HWSZ / 4 + threads - 1) / threads;
        clear_winner_kernel<<<blocks, threads>>>();
    }
}

// round 9
// speedup vs baseline: 1.0458x; 1.0458x over previous
#include <cuda_runtime.h>
#include <cstdint>

// Problem constants (fixed by the reference)
#define HH 1024
#define WW 1024
#define HWSZ (HH * WW)      // 1,048,576 cells
#define NF 64               // features
#define NP 100000           // pillars

// Per-cell winner, encoded as (pillar_index + 1); 0 == empty.
// BSS zero-init makes the very first call correct; clear_winner_kernel
// (launched after gather) restores the all-empty state for the next replay.
__device__ __align__(16) int g_winner[HWSZ];

// coords is int32 on device (JAX x64-off materializes int64 as int32).
// Layout [NP, 3]: x = col 2, y = col 1. Last-writer-wins == max pillar idx.
// 128-thread blocks -> 782 blocks for better wave spread (latency-bound).
__global__ __launch_bounds__(128) void scatter_winner_kernel(
        const int* __restrict__ coords) {
    int p = blockIdx.x * blockDim.x + threadIdx.x;
    if (p >= NP) return;
    int x = coords[3 * p + 2];
    int y = coords[3 * p + 1];
    if (x >= 0 && x < WW && y >= 0 && y < HH) {
        atomicMax(&g_winner[y * WW + x], p + 1);
    }
}

// Block = 256 threads = 16 cell-groups x 16 feature-chunks (one tile each,
// full 4M-thread concurrency like the 49.7us design), but the block's 16
// winner int4s are loaded from global ONCE and broadcast via smem:
// winner global traffic 64MB -> 4MB while per-thread store work is identical.
// Output stores evict-first (.cs) to keep feat rows L2-resident.
__global__ __launch_bounds__(256) void gather_out_kernel(
        const float* __restrict__ feat,
        float* __restrict__ out) {
    __shared__ int4 s_w[16];

    int tid = threadIdx.x;
    int grp = tid & 15;         // cell-group within block (0..15)
    int f4  = tid >> 4;         // feature chunk (0..15)
    int gbase = blockIdx.x * 16;          // first cell-group of this block
    int c0 = (gbase + grp) * 4;           // first cell of this thread's group

    if (tid < 16) {
        s_w[tid] = __ldg(reinterpret_cast<const int4*>(
            &g_winner[(gbase + tid) * 4]));
    }
    __syncthreads();

    int4 w4 = s_w[grp];
    int w[4] = {w4.x, w4.y, w4.z, w4.w};

    float4 v[4];
    #pragma unroll
    for (int j = 0; j < 4; j++) {
        if (w[j] > 0) {
            v[j] = __ldg(reinterpret_cast<const float4*>(
                feat + (size_t)(w[j] - 1) * NF + f4 * 4));
        } else {
            v[j] = make_float4(0.f, 0.f, 0.f, 0.f);
        }
    }
    #pragma unroll
    for (int k = 0; k < 4; k++) {
        float4 o;
        o.x = reinterpret_cast<const float*>(&v[0])[k];
        o.y = reinterpret_cast<const float*>(&v[1])[k];
        o.z = reinterpret_cast<const float*>(&v[2])[k];
        o.w = reinterpret_cast<const float*>(&v[3])[k];
        __stcs(reinterpret_cast<float4*>(
            out + (size_t)(f4 * 4 + k) * HWSZ + c0), o);
    }
}

// Restore the all-empty winner state for the next graph replay.
__global__ __launch_bounds__(512) void clear_winner_kernel() {
    int i = blockIdx.x * blockDim.x + threadIdx.x;
    if (i < HWSZ / 4) {
        reinterpret_cast<int4*>(g_winner)[i] = make_int4(0, 0, 0, 0);
    }
}

extern "C" void kernel_launch(void* const* d_in, const int* in_sizes, int n_in,
                              void* d_out, int out_size) {
    const float* pillar_features = (const float*)d_in[0]; // [NP, 64] f32
    const int*   coords          = (const int*)d_in[1];   // [NP, 3] i32
    float*       out             = (float*)d_out;         // [1,64,1024,1024] f32

    {
        int threads = 128;
        int blocks = (NP + threads - 1) / threads;
        scatter_winner_kernel<<<blocks, threads>>>(coords);
    }
    {
        // (HWSZ/4) cell-groups, 16 per block -> 16384 blocks of 256 threads.
        int blocks = (HWSZ / 4) / 16;
        gather_out_kernel<<<blocks, 256>>>(pillar_features, out);
    }
    {
        int threads = 512;
        int blocks = (HWSZ / 4 + threads - 1) / threads;
        clear_winner_kernel<<<blocks, threads>>>();
    }
}